// round 5
// baseline (speedup 1.0000x reference)
#include <cuda_runtime.h>
#include <cuda_bf16.h>
#include <cstdint>

// VQ encoder, int8-IMMA, fused-prep, 128x256-tile edition.
//  1) fused per-row stats + int8 quant of z (one read); fused codebook norm + quant
//  2) IMMA s8 GEMM (128x256 tiles, 3-stage cp.async): s = c2 - dq_r*dot -> g_sb (bf16), row min
//  3) scan: candidates with s <= rowmin + TAU
//  4) exact fp32 recheck (R1's verified expression + packed first-index tie-break)
//  5) outputs: quantized_st, loss, indices

#define M_ROWS 16384
#define N_CODES 8192
#define K_DIM   1024
#define OUT_Q_ELEMS 16777216
#define OUT_LOSS_POS 16777216
#define OUT_IDX_POS  16777217

#define CAP 512
#define TAU 1.5e-3f

#define TM 128
#define TN 256
#define KC 64
#define NKC (K_DIM / KC)      // 16
#define BSTRIDE 80
#define NSTAGE 3
#define STAGE_BYTES ((TM + TN) * BSTRIDE)       // 30720
#define SMEM_DYN (NSTAGE * STAGE_BYTES)         // 92160

// ---------------------------------------------------------------- device scratch
__device__ int8_t g_z8[(size_t)M_ROWS * K_DIM];          // 16 MB
__device__ int8_t g_c8[(size_t)N_CODES * K_DIM];         // 8 MB
__device__ __nv_bfloat16 g_sb[(size_t)M_ROWS * N_CODES]; // 256 MB
__device__ unsigned g_sminu[M_ROWS];
__device__ int g_ccnt[M_ROWS];
__device__ int g_cand[(size_t)M_ROWS * CAP];
__device__ unsigned long long g_best[M_ROWS];
__device__ float g_z2[M_ROWS];
__device__ float g_zdq[M_ROWS];     // 2 * rowmax / (127*127*8192)
__device__ float g_c2[N_CODES];
__device__ float g_rowloss[M_ROWS];

// ---------------------------------------------------------------- helpers
__device__ __forceinline__ uint32_t smem_u32(const void* p) {
    uint32_t a;
    asm("{ .reg .u64 t; cvta.to.shared.u64 t, %1; cvt.u32.u64 %0, t; }" : "=r"(a) : "l"(p));
    return a;
}
__device__ __forceinline__ void cp_async16(uint32_t dst, const void* src) {
    asm volatile("cp.async.cg.shared.global [%0], [%1], 16;" :: "r"(dst), "l"(src) : "memory");
}
__device__ __forceinline__ unsigned fmap(float f) {
    unsigned b = __float_as_uint(f);
    return (b & 0x80000000u) ? ~b : (b | 0x80000000u);
}
__device__ __forceinline__ float funmap(unsigned u) {
    return (u & 0x80000000u) ? __uint_as_float(u & 0x7FFFFFFFu) : __uint_as_float(~u);
}
__device__ __forceinline__ void mma_s8(int* c, const uint32_t* a, uint32_t b0, uint32_t b1) {
    asm volatile(
        "mma.sync.aligned.m16n8k32.row.col.s32.s8.s8.s32 "
        "{%0,%1,%2,%3}, {%4,%5,%6,%7}, {%8,%9}, {%0,%1,%2,%3};"
        : "+r"(c[0]), "+r"(c[1]), "+r"(c[2]), "+r"(c[3])
        : "r"(a[0]), "r"(a[1]), "r"(a[2]), "r"(a[3]), "r"(b0), "r"(b1));
}

// ---------------------------------------------------------------- fused prep
// one block per z row: read row once -> z2, rowmax, scales, int8 quant, init row state
__global__ void __launch_bounds__(256) k_prep_z(const float* __restrict__ z) {
    __shared__ float ssum[8], smax[8];
    int row = blockIdx.x, t = threadIdx.x, lane = t & 31, wid = t >> 5;
    float4 v = ((const float4*)(z + (size_t)row * K_DIM))[t];
    float s = v.x*v.x + v.y*v.y + v.z*v.z + v.w*v.w;
    float mx = fmaxf(fmaxf(fabsf(v.x), fabsf(v.y)), fmaxf(fabsf(v.z), fabsf(v.w)));
    #pragma unroll
    for (int o = 16; o > 0; o >>= 1) {
        s  += __shfl_down_sync(0xffffffffu, s, o);
        mx = fmaxf(mx, __shfl_down_sync(0xffffffffu, mx, o));
    }
    if (lane == 0) { ssum[wid] = s; smax[wid] = mx; }
    __syncthreads();
    if (t == 0) {
        float ts = 0.f, tm = 0.f;
        #pragma unroll
        for (int i = 0; i < 8; i++) { ts += ssum[i]; tm = fmaxf(tm, smax[i]); }
        tm = fmaxf(tm, 1e-20f);
        g_z2[row] = ts;
        g_zdq[row] = 2.f * tm / (127.f * 127.f * 8192.f);
        ssum[0] = 127.f / tm;                        // broadcast scale
        g_sminu[row] = 0xFFFFFFFFu;
        g_ccnt[row] = 0;
    }
    __syncthreads();
    float sc = ssum[0];
    char4 o;
    o.x = (char)__float2int_rn(v.x * sc);
    o.y = (char)__float2int_rn(v.y * sc);
    o.z = (char)__float2int_rn(v.z * sc);
    o.w = (char)__float2int_rn(v.w * sc);
    ((char4*)(g_z8 + (size_t)row * K_DIM))[t] = o;
}

// one block per codebook row: c2 + int8 quant (exact global scale)
__global__ void __launch_bounds__(256) k_prep_c(const float* __restrict__ cb) {
    __shared__ float ssum[8];
    int row = blockIdx.x, t = threadIdx.x, lane = t & 31, wid = t >> 5;
    float4 v = ((const float4*)(cb + (size_t)row * K_DIM))[t];
    float s = fmaf(v.x, v.x, fmaf(v.y, v.y, fmaf(v.z, v.z, v.w * v.w)));
    #pragma unroll
    for (int o = 16; o > 0; o >>= 1) s += __shfl_down_sync(0xffffffffu, s, o);
    if (lane == 0) ssum[wid] = s;
    __syncthreads();
    if (t == 0) {
        float ts = 0.f;
        #pragma unroll
        for (int i = 0; i < 8; i++) ts += ssum[i];
        g_c2[row] = ts;
    }
    const float sc = 127.f * 8192.f;
    char4 o;
    o.x = (char)__float2int_rn(v.x * sc);
    o.y = (char)__float2int_rn(v.y * sc);
    o.z = (char)__float2int_rn(v.z * sc);
    o.w = (char)__float2int_rn(v.w * sc);
    ((char4*)(g_c8 + (size_t)row * K_DIM))[t] = o;
}

// NOTE: c2 computed here with a nested-fma quad; the EXACT recheck uses g_c2 only inside
// d = (z2+c2)-2m which the reference also computes from float32 sums; sum order differs from
// R1's k_rownorm_c, so keep R1's exact loop for safety:
__global__ void k_rownorm_c_exact(const float* __restrict__ cb) {
    int w = (blockIdx.x * blockDim.x + threadIdx.x) >> 5, lane = threadIdx.x & 31;
    if (w >= N_CODES) return;
    const float* r = cb + (size_t)w * K_DIM;
    float s = 0.f;
    #pragma unroll 4
    for (int j = lane; j < K_DIM; j += 32) { float v = r[j]; s = fmaf(v, v, s); }
    #pragma unroll
    for (int o = 16; o > 0; o >>= 1) s += __shfl_down_sync(0xffffffffu, s, o);
    if (lane == 0) g_c2[w] = s;
}

// ---------------------------------------------------------------- IMMA GEMM
// 128x256 tile, KC=64, 256 threads (8 warps 2x4 -> warp tile 64x64),
// 3-stage cp.async, ldmatrix from stride-80 smem.
__global__ void __launch_bounds__(256, 1) k_gemm() {
    extern __shared__ uint8_t dynsm[];
    __shared__ float sC2[TN];

    const int t = threadIdx.x;
    const int wid = t >> 5, lane = t & 31;
    const int warpm = (wid & 1) * 64;        // 2 warps over M
    const int warpn = (wid >> 1) * 64;       // 4 warps over N
    const int colBase = blockIdx.x * TN;
    const int rowBase = blockIdx.y * TM;

    sC2[t] = g_c2[colBase + t];

    int acc[4][8][4];
    #pragma unroll
    for (int mf = 0; mf < 4; mf++)
        #pragma unroll
        for (int nf = 0; nf < 8; nf++)
            #pragma unroll
            for (int q = 0; q < 4; q++) acc[mf][nf][q] = 0;

    auto sA = [&](int s) -> uint8_t* { return dynsm + s * STAGE_BYTES; };
    auto sB = [&](int s) -> uint8_t* { return dynsm + s * STAGE_BYTES + TM * BSTRIDE; };

    const int lrow = t >> 2, lquad = t & 3;
    auto load_stage = [&](int s, int c) {
        int kc = c * KC;
        #pragma unroll
        for (int u = 0; u < 2; u++) {                // A: 128 rows
            int row = lrow + u * 64;
            cp_async16(smem_u32(sA(s) + row * BSTRIDE + lquad * 16),
                       &g_z8[(size_t)(rowBase + row) * K_DIM + kc + lquad * 16]);
        }
        #pragma unroll
        for (int u = 0; u < 4; u++) {                // B: 256 rows
            int row = lrow + u * 64;
            cp_async16(smem_u32(sB(s) + row * BSTRIDE + lquad * 16),
                       &g_c8[(size_t)(colBase + row) * K_DIM + kc + lquad * 16]);
        }
        asm volatile("cp.async.commit_group;" ::: "memory");
    };

    load_stage(0, 0);
    load_stage(1, 1);
    for (int c = 0; c < NKC; c++) {
        asm volatile("cp.async.wait_group 1;" ::: "memory");
        __syncthreads();
        if (c + 2 < NKC) load_stage((c + 2) % NSTAGE, c + 2);
        int s = c % NSTAGE;
        #pragma unroll
        for (int ks = 0; ks < 2; ks++) {
            int kk = ks * 32;
            uint32_t afr[4][4];
            #pragma unroll
            for (int mf = 0; mf < 4; mf++) {
                int row = warpm + mf * 16 + (lane & 15);
                int col = kk + ((lane >> 4) << 4);
                uint32_t ad = smem_u32(sA(s) + row * BSTRIDE + col);
                asm volatile("ldmatrix.sync.aligned.m8n8.x4.shared.b16 {%0,%1,%2,%3}, [%4];"
                    : "=r"(afr[mf][0]), "=r"(afr[mf][1]), "=r"(afr[mf][2]), "=r"(afr[mf][3])
                    : "r"(ad));
            }
            #pragma unroll
            for (int np = 0; np < 4; np++) {
                int grp = lane >> 3, lr = lane & 7;
                int nrow = warpn + np * 16 + ((grp >> 1) << 3) + lr;
                int kcol = kk + ((grp & 1) << 4);
                uint32_t bd = smem_u32(sB(s) + nrow * BSTRIDE + kcol);
                uint32_t b[4];
                asm volatile("ldmatrix.sync.aligned.m8n8.x4.shared.b16 {%0,%1,%2,%3}, [%4];"
                    : "=r"(b[0]), "=r"(b[1]), "=r"(b[2]), "=r"(b[3]) : "r"(bd));
                #pragma unroll
                for (int mf = 0; mf < 4; mf++) {
                    mma_s8(acc[mf][np * 2 + 0], afr[mf], b[0], b[1]);
                    mma_s8(acc[mf][np * 2 + 1], afr[mf], b[2], b[3]);
                }
            }
        }
        __syncthreads();
    }

    // epilogue: s = c2 - dq_row * dot ; store bf16 ; per-row fp32 min
    #pragma unroll
    for (int mf = 0; mf < 4; mf++) {
        int row0 = rowBase + warpm + mf * 16 + (lane >> 2);
        float dq0 = g_zdq[row0], dq1 = g_zdq[row0 + 8];
        float v0 = 3.4e38f, v1 = 3.4e38f;
        #pragma unroll
        for (int nf = 0; nf < 8; nf++) {
            int lc = warpn + nf * 8 + (lane & 3) * 2;
            float c2a = sC2[lc], c2b = sC2[lc + 1];
            float s0 = c2a - dq0 * (float)acc[mf][nf][0];
            float s1 = c2b - dq0 * (float)acc[mf][nf][1];
            float s2 = c2a - dq1 * (float)acc[mf][nf][2];
            float s3 = c2b - dq1 * (float)acc[mf][nf][3];
            *(__nv_bfloat162*)&g_sb[(size_t)row0 * N_CODES + colBase + lc] =
                __nv_bfloat162(__float2bfloat16(s0), __float2bfloat16(s1));
            *(__nv_bfloat162*)&g_sb[(size_t)(row0 + 8) * N_CODES + colBase + lc] =
                __nv_bfloat162(__float2bfloat16(s2), __float2bfloat16(s3));
            v0 = fminf(v0, fminf(s0, s1));
            v1 = fminf(v1, fminf(s2, s3));
        }
        v0 = fminf(v0, __shfl_xor_sync(0xffffffffu, v0, 1));
        v0 = fminf(v0, __shfl_xor_sync(0xffffffffu, v0, 2));
        v1 = fminf(v1, __shfl_xor_sync(0xffffffffu, v1, 1));
        v1 = fminf(v1, __shfl_xor_sync(0xffffffffu, v1, 2));
        if ((lane & 3) == 0) {
            atomicMin(&g_sminu[row0], fmap(v0));
            atomicMin(&g_sminu[row0 + 8], fmap(v1));
        }
    }
}

// ---------------------------------------------------------------- candidate scan
__global__ void k_scan() {
    int w = (blockIdx.x * blockDim.x + threadIdx.x) >> 5, lane = threadIdx.x & 31;
    if (w >= M_ROWS) return;
    float thr = funmap(g_sminu[w]) + TAU;
    const uint4* srow = (const uint4*)(g_sb + (size_t)w * N_CODES);
    for (int cidx = lane; cidx < N_CODES / 8; cidx += 32) {
        uint4 u = srow[cidx];
        uint32_t words[4] = {u.x, u.y, u.z, u.w};
        #pragma unroll
        for (int q = 0; q < 4; q++) {
            __nv_bfloat162 p = *(__nv_bfloat162*)&words[q];
            float a = __bfloat162float(p.x), b = __bfloat162float(p.y);
            if (a <= thr) {
                int slot = atomicAdd(&g_ccnt[w], 1);
                if (slot < CAP) g_cand[(size_t)w * CAP + slot] = cidx * 8 + q * 2;
            }
            if (b <= thr) {
                int slot = atomicAdd(&g_ccnt[w], 1);
                if (slot < CAP) g_cand[(size_t)w * CAP + slot] = cidx * 8 + q * 2 + 1;
            }
        }
    }
}

// ---------------------------------------------------------------- exact recheck
__global__ void k_recheck(const float* __restrict__ z, const float* __restrict__ cb) {
    int w = (blockIdx.x * blockDim.x + threadIdx.x) >> 5, lane = threadIdx.x & 31;
    if (w >= M_ROWS) return;
    const float* zr = z + (size_t)w * K_DIM;
    float zz = g_z2[w];
    int n = g_ccnt[w];
    unsigned long long best = ~0ULL;
    if (n <= CAP) {
        for (int i = 0; i < n; i++) {
            int cc = g_cand[(size_t)w * CAP + i];
            const float* cr = cb + (size_t)cc * K_DIM;
            float m = 0.f;
            #pragma unroll 4
            for (int j = lane; j < K_DIM; j += 32) m = fmaf(zr[j], cr[j], m);
            #pragma unroll
            for (int o = 16; o > 0; o >>= 1) m += __shfl_down_sync(0xffffffffu, m, o);
            if (lane == 0) {
                float d = (zz + g_c2[cc]) - 2.0f * m;
                unsigned long long p =
                    ((unsigned long long)__float_as_uint(d) << 32) | (unsigned)cc;
                best = (p < best) ? p : best;
            }
        }
    } else {    // overflow fallback: exact full scan
        for (int cc = 0; cc < N_CODES; cc++) {
            const float* cr = cb + (size_t)cc * K_DIM;
            float m = 0.f;
            for (int j = lane; j < K_DIM; j += 32) m = fmaf(zr[j], cr[j], m);
            #pragma unroll
            for (int o = 16; o > 0; o >>= 1) m += __shfl_down_sync(0xffffffffu, m, o);
            if (lane == 0) {
                float d = (zz + g_c2[cc]) - 2.0f * m;
                unsigned long long p =
                    ((unsigned long long)__float_as_uint(d) << 32) | (unsigned)cc;
                best = (p < best) ? p : best;
            }
        }
    }
    if (lane == 0) g_best[w] = best;
}

// ---------------------------------------------------------------- outputs
__global__ void k_output(const float* __restrict__ z, const float* __restrict__ cb,
                         float* __restrict__ out, int out_size) {
    int w = (blockIdx.x * blockDim.x + threadIdx.x) >> 5, lane = threadIdx.x & 31;
    if (w >= M_ROWS) return;
    int idx = (int)(g_best[w] & 0xFFFFFFFFULL);
    if (lane == 0) {
        int p = OUT_IDX_POS + w;
        if (p < out_size) out[p] = (float)idx;
    }
    const float* zr = z + (size_t)w * K_DIM;
    const float* qr = cb + (size_t)idx * K_DIM;
    float* orow = out + (size_t)w * K_DIM;
    float s = 0.f;
    #pragma unroll 4
    for (int j = lane; j < K_DIM; j += 32) {
        float zv = zr[j], qv = qr[j];
        orow[j] = zv + (qv - zv);
        float dl = zv - qv;
        s = fmaf(dl, dl, s);
    }
    #pragma unroll
    for (int o = 16; o > 0; o >>= 1) s += __shfl_down_sync(0xffffffffu, s, o);
    if (lane == 0) g_rowloss[w] = s;
}
__global__ void k_loss(float* __restrict__ out, int out_size) {
    __shared__ double sd[256];
    int t = threadIdx.x;
    double s = 0.0;
    for (int i = t; i < M_ROWS; i += 256) s += (double)g_rowloss[i];
    sd[t] = s;
    __syncthreads();
    #pragma unroll
    for (int off = 128; off > 0; off >>= 1) {
        if (t < off) sd[t] += sd[t + off];
        __syncthreads();
    }
    if (t == 0 && OUT_LOSS_POS < out_size) {
        double mean = sd[0] / (double)OUT_Q_ELEMS;
        float Mf = (float)mean;
        out[OUT_LOSS_POS] = 0.25f * Mf + Mf;
    }
}

// ---------------------------------------------------------------- launch
extern "C" void kernel_launch(void* const* d_in, const int* in_sizes, int n_in,
                              void* d_out, int out_size) {
    const float* z  = (const float*)d_in[0];
    const float* cb = (const float*)d_in[1];
    float* out = (float*)d_out;
    (void)in_sizes; (void)n_in;

    cudaFuncSetAttribute(k_gemm, cudaFuncAttributeMaxDynamicSharedMemorySize, SMEM_DYN);

    k_prep_z<<<M_ROWS, 256>>>(z);
    k_prep_c<<<N_CODES, 256>>>(cb);
    k_rownorm_c_exact<<<(N_CODES * 32 + 255) / 256, 256>>>(cb);  // exact c2 for recheck

    dim3 grid(N_CODES / TN, M_ROWS / TM);   // (32, 128)
    k_gemm<<<grid, 256, SMEM_DYN>>>();

    k_scan<<<(M_ROWS * 32) / 256, 256>>>();
    k_recheck<<<(M_ROWS * 32) / 256, 256>>>(z, cb);
    k_output<<<(M_ROWS * 32 + 255) / 256, 256>>>(z, cb, out, out_size);
    k_loss<<<1, 256>>>(out, out_size);
}

// round 6
// speedup vs baseline: 1.0209x; 1.0209x over previous
#include <cuda_runtime.h>
#include <cuda_bf16.h>
#include <cstdint>

// VQ encoder, int8-IMMA, 128x256 tile / 512 threads (16 warps) edition.
//  1) fused per-row stats + int8 quant of z; fused codebook quant (+ exact c2 pass)
//  2) IMMA s8 GEMM (128x256 tiles, 3-stage cp.async): s = c2 - dq_r*dot -> g_sb (bf16), row min
//  3) scan: candidates with s <= rowmin + TAU
//  4) exact fp32 recheck (R1's verified expression + packed first-index tie-break)
//  5) outputs: quantized_st, loss, indices

#define M_ROWS 16384
#define N_CODES 8192
#define K_DIM   1024
#define OUT_Q_ELEMS 16777216
#define OUT_LOSS_POS 16777216
#define OUT_IDX_POS  16777217

#define CAP 512
#define TAU 1.5e-3f

#define TM 128
#define TN 256
#define KC 64
#define NKC (K_DIM / KC)      // 16
#define BSTRIDE 80
#define NSTAGE 3
#define STAGE_BYTES ((TM + TN) * BSTRIDE)       // 30720
#define SMEM_DYN (NSTAGE * STAGE_BYTES)         // 92160
#define NTHREADS 512

// ---------------------------------------------------------------- device scratch
__device__ int8_t g_z8[(size_t)M_ROWS * K_DIM];          // 16 MB
__device__ int8_t g_c8[(size_t)N_CODES * K_DIM];         // 8 MB
__device__ __nv_bfloat16 g_sb[(size_t)M_ROWS * N_CODES]; // 256 MB
__device__ unsigned g_sminu[M_ROWS];
__device__ int g_ccnt[M_ROWS];
__device__ int g_cand[(size_t)M_ROWS * CAP];
__device__ unsigned long long g_best[M_ROWS];
__device__ float g_z2[M_ROWS];
__device__ float g_zdq[M_ROWS];
__device__ float g_c2[N_CODES];
__device__ float g_rowloss[M_ROWS];

// ---------------------------------------------------------------- helpers
__device__ __forceinline__ uint32_t smem_u32(const void* p) {
    uint32_t a;
    asm("{ .reg .u64 t; cvta.to.shared.u64 t, %1; cvt.u32.u64 %0, t; }" : "=r"(a) : "l"(p));
    return a;
}
__device__ __forceinline__ void cp_async16(uint32_t dst, const void* src) {
    asm volatile("cp.async.cg.shared.global [%0], [%1], 16;" :: "r"(dst), "l"(src) : "memory");
}
__device__ __forceinline__ unsigned fmap(float f) {
    unsigned b = __float_as_uint(f);
    return (b & 0x80000000u) ? ~b : (b | 0x80000000u);
}
__device__ __forceinline__ float funmap(unsigned u) {
    return (u & 0x80000000u) ? __uint_as_float(u & 0x7FFFFFFFu) : __uint_as_float(~u);
}
__device__ __forceinline__ void mma_s8(int* c, const uint32_t* a, uint32_t b0, uint32_t b1) {
    asm volatile(
        "mma.sync.aligned.m16n8k32.row.col.s32.s8.s8.s32 "
        "{%0,%1,%2,%3}, {%4,%5,%6,%7}, {%8,%9}, {%0,%1,%2,%3};"
        : "+r"(c[0]), "+r"(c[1]), "+r"(c[2]), "+r"(c[3])
        : "r"(a[0]), "r"(a[1]), "r"(a[2]), "r"(a[3]), "r"(b0), "r"(b1));
}

// ---------------------------------------------------------------- fused prep
__global__ void __launch_bounds__(256) k_prep_z(const float* __restrict__ z) {
    __shared__ float ssum[8], smax[8];
    int row = blockIdx.x, t = threadIdx.x, lane = t & 31, wid = t >> 5;
    float4 v = ((const float4*)(z + (size_t)row * K_DIM))[t];
    float s = v.x*v.x + v.y*v.y + v.z*v.z + v.w*v.w;
    float mx = fmaxf(fmaxf(fabsf(v.x), fabsf(v.y)), fmaxf(fabsf(v.z), fabsf(v.w)));
    #pragma unroll
    for (int o = 16; o > 0; o >>= 1) {
        s  += __shfl_down_sync(0xffffffffu, s, o);
        mx = fmaxf(mx, __shfl_down_sync(0xffffffffu, mx, o));
    }
    if (lane == 0) { ssum[wid] = s; smax[wid] = mx; }
    __syncthreads();
    if (t == 0) {
        float ts = 0.f, tm = 0.f;
        #pragma unroll
        for (int i = 0; i < 8; i++) { ts += ssum[i]; tm = fmaxf(tm, smax[i]); }
        tm = fmaxf(tm, 1e-20f);
        g_z2[row] = ts;
        g_zdq[row] = 2.f * tm / (127.f * 127.f * 8192.f);
        ssum[0] = 127.f / tm;
        g_sminu[row] = 0xFFFFFFFFu;
        g_ccnt[row] = 0;
    }
    __syncthreads();
    float sc = ssum[0];
    char4 o;
    o.x = (char)__float2int_rn(v.x * sc);
    o.y = (char)__float2int_rn(v.y * sc);
    o.z = (char)__float2int_rn(v.z * sc);
    o.w = (char)__float2int_rn(v.w * sc);
    ((char4*)(g_z8 + (size_t)row * K_DIM))[t] = o;
}

__global__ void __launch_bounds__(256) k_prep_c(const float* __restrict__ cb) {
    int i = blockIdx.x * blockDim.x + threadIdx.x;
    const float sc = 127.f * 8192.f;
    float4 v = ((const float4*)cb)[i];
    char4 o;
    o.x = (char)__float2int_rn(v.x * sc);
    o.y = (char)__float2int_rn(v.y * sc);
    o.z = (char)__float2int_rn(v.z * sc);
    o.w = (char)__float2int_rn(v.w * sc);
    ((char4*)g_c8)[i] = o;
}

// exact c2 in R1's verified accumulation order (feeds exact recheck)
__global__ void k_rownorm_c_exact(const float* __restrict__ cb) {
    int w = (blockIdx.x * blockDim.x + threadIdx.x) >> 5, lane = threadIdx.x & 31;
    if (w >= N_CODES) return;
    const float* r = cb + (size_t)w * K_DIM;
    float s = 0.f;
    #pragma unroll 4
    for (int j = lane; j < K_DIM; j += 32) { float v = r[j]; s = fmaf(v, v, s); }
    #pragma unroll
    for (int o = 16; o > 0; o >>= 1) s += __shfl_down_sync(0xffffffffu, s, o);
    if (lane == 0) g_c2[w] = s;
}

// ---------------------------------------------------------------- IMMA GEMM
// 128x256 tile, 512 threads (16 warps, 4x4 -> warp tile 32x64), 3-stage cp.async.
__global__ void __launch_bounds__(NTHREADS, 1) k_gemm() {
    extern __shared__ uint8_t dynsm[];
    __shared__ float sC2[TN];

    const int t = threadIdx.x;
    const int wid = t >> 5, lane = t & 31;
    const int warpm = (wid & 3) * 32;        // 4 warps over M
    const int warpn = (wid >> 2) * 64;       // 4 warps over N
    const int colBase = blockIdx.x * TN;
    const int rowBase = blockIdx.y * TM;

    if (t < TN) sC2[t] = g_c2[colBase + t];

    int acc[2][8][4];
    #pragma unroll
    for (int mf = 0; mf < 2; mf++)
        #pragma unroll
        for (int nf = 0; nf < 8; nf++)
            #pragma unroll
            for (int q = 0; q < 4; q++) acc[mf][nf][q] = 0;

    auto sA = [&](int s) -> uint8_t* { return dynsm + s * STAGE_BYTES; };
    auto sB = [&](int s) -> uint8_t* { return dynsm + s * STAGE_BYTES + TM * BSTRIDE; };

    const int lrow = t >> 2, lquad = t & 3;   // 128 rows per pass at 512 threads
    auto load_stage = [&](int s, int c) {
        int kc = c * KC;
        cp_async16(smem_u32(sA(s) + lrow * BSTRIDE + lquad * 16),
                   &g_z8[(size_t)(rowBase + lrow) * K_DIM + kc + lquad * 16]);
        #pragma unroll
        for (int u = 0; u < 2; u++) {
            int row = lrow + u * 128;
            cp_async16(smem_u32(sB(s) + row * BSTRIDE + lquad * 16),
                       &g_c8[(size_t)(colBase + row) * K_DIM + kc + lquad * 16]);
        }
        asm volatile("cp.async.commit_group;" ::: "memory");
    };

    load_stage(0, 0);
    load_stage(1, 1);
    for (int c = 0; c < NKC; c++) {
        asm volatile("cp.async.wait_group 1;" ::: "memory");
        __syncthreads();
        if (c + 2 < NKC) load_stage((c + 2) % NSTAGE, c + 2);
        int s = c % NSTAGE;
        #pragma unroll
        for (int ks = 0; ks < 2; ks++) {
            int kk = ks * 32;
            uint32_t afr[2][4];
            #pragma unroll
            for (int mf = 0; mf < 2; mf++) {
                int row = warpm + mf * 16 + (lane & 15);
                int col = kk + ((lane >> 4) << 4);
                uint32_t ad = smem_u32(sA(s) + row * BSTRIDE + col);
                asm volatile("ldmatrix.sync.aligned.m8n8.x4.shared.b16 {%0,%1,%2,%3}, [%4];"
                    : "=r"(afr[mf][0]), "=r"(afr[mf][1]), "=r"(afr[mf][2]), "=r"(afr[mf][3])
                    : "r"(ad));
            }
            #pragma unroll
            for (int np = 0; np < 4; np++) {
                int grp = lane >> 3, lr = lane & 7;
                int nrow = warpn + np * 16 + ((grp >> 1) << 3) + lr;
                int kcol = kk + ((grp & 1) << 4);
                uint32_t bd = smem_u32(sB(s) + nrow * BSTRIDE + kcol);
                uint32_t b[4];
                asm volatile("ldmatrix.sync.aligned.m8n8.x4.shared.b16 {%0,%1,%2,%3}, [%4];"
                    : "=r"(b[0]), "=r"(b[1]), "=r"(b[2]), "=r"(b[3]) : "r"(bd));
                #pragma unroll
                for (int mf = 0; mf < 2; mf++) {
                    mma_s8(acc[mf][np * 2 + 0], afr[mf], b[0], b[1]);
                    mma_s8(acc[mf][np * 2 + 1], afr[mf], b[2], b[3]);
                }
            }
        }
        __syncthreads();
    }

    // epilogue: s = c2 - dq_row * dot ; store bf16 ; per-row fp32 min
    #pragma unroll
    for (int mf = 0; mf < 2; mf++) {
        int row0 = rowBase + warpm + mf * 16 + (lane >> 2);
        float dq0 = g_zdq[row0], dq1 = g_zdq[row0 + 8];
        float v0 = 3.4e38f, v1 = 3.4e38f;
        #pragma unroll
        for (int nf = 0; nf < 8; nf++) {
            int lc = warpn + nf * 8 + (lane & 3) * 2;
            float c2a = sC2[lc], c2b = sC2[lc + 1];
            float s0 = c2a - dq0 * (float)acc[mf][nf][0];
            float s1 = c2b - dq0 * (float)acc[mf][nf][1];
            float s2 = c2a - dq1 * (float)acc[mf][nf][2];
            float s3 = c2b - dq1 * (float)acc[mf][nf][3];
            *(__nv_bfloat162*)&g_sb[(size_t)row0 * N_CODES + colBase + lc] =
                __nv_bfloat162(__float2bfloat16(s0), __float2bfloat16(s1));
            *(__nv_bfloat162*)&g_sb[(size_t)(row0 + 8) * N_CODES + colBase + lc] =
                __nv_bfloat162(__float2bfloat16(s2), __float2bfloat16(s3));
            v0 = fminf(v0, fminf(s0, s1));
            v1 = fminf(v1, fminf(s2, s3));
        }
        v0 = fminf(v0, __shfl_xor_sync(0xffffffffu, v0, 1));
        v0 = fminf(v0, __shfl_xor_sync(0xffffffffu, v0, 2));
        v1 = fminf(v1, __shfl_xor_sync(0xffffffffu, v1, 1));
        v1 = fminf(v1, __shfl_xor_sync(0xffffffffu, v1, 2));
        if ((lane & 3) == 0) {
            atomicMin(&g_sminu[row0], fmap(v0));
            atomicMin(&g_sminu[row0 + 8], fmap(v1));
        }
    }
}

// ---------------------------------------------------------------- candidate scan
__global__ void k_scan() {
    int w = (blockIdx.x * blockDim.x + threadIdx.x) >> 5, lane = threadIdx.x & 31;
    if (w >= M_ROWS) return;
    float thr = funmap(g_sminu[w]) + TAU;
    const uint4* srow = (const uint4*)(g_sb + (size_t)w * N_CODES);
    for (int cidx = lane; cidx < N_CODES / 8; cidx += 32) {
        uint4 u = srow[cidx];
        uint32_t words[4] = {u.x, u.y, u.z, u.w};
        #pragma unroll
        for (int q = 0; q < 4; q++) {
            __nv_bfloat162 p = *(__nv_bfloat162*)&words[q];
            float a = __bfloat162float(p.x), b = __bfloat162float(p.y);
            if (a <= thr) {
                int slot = atomicAdd(&g_ccnt[w], 1);
                if (slot < CAP) g_cand[(size_t)w * CAP + slot] = cidx * 8 + q * 2;
            }
            if (b <= thr) {
                int slot = atomicAdd(&g_ccnt[w], 1);
                if (slot < CAP) g_cand[(size_t)w * CAP + slot] = cidx * 8 + q * 2 + 1;
            }
        }
    }
}

// ---------------------------------------------------------------- exact recheck
__global__ void k_recheck(const float* __restrict__ z, const float* __restrict__ cb) {
    int w = (blockIdx.x * blockDim.x + threadIdx.x) >> 5, lane = threadIdx.x & 31;
    if (w >= M_ROWS) return;
    const float* zr = z + (size_t)w * K_DIM;
    float zz = g_z2[w];
    int n = g_ccnt[w];
    unsigned long long best = ~0ULL;
    if (n <= CAP) {
        for (int i = 0; i < n; i++) {
            int cc = g_cand[(size_t)w * CAP + i];
            const float* cr = cb + (size_t)cc * K_DIM;
            float m = 0.f;
            #pragma unroll 4
            for (int j = lane; j < K_DIM; j += 32) m = fmaf(zr[j], cr[j], m);
            #pragma unroll
            for (int o = 16; o > 0; o >>= 1) m += __shfl_down_sync(0xffffffffu, m, o);
            if (lane == 0) {
                float d = (zz + g_c2[cc]) - 2.0f * m;
                unsigned long long p =
                    ((unsigned long long)__float_as_uint(d) << 32) | (unsigned)cc;
                best = (p < best) ? p : best;
            }
        }
    } else {
        for (int cc = 0; cc < N_CODES; cc++) {
            const float* cr = cb + (size_t)cc * K_DIM;
            float m = 0.f;
            for (int j = lane; j < K_DIM; j += 32) m = fmaf(zr[j], cr[j], m);
            #pragma unroll
            for (int o = 16; o > 0; o >>= 1) m += __shfl_down_sync(0xffffffffu, m, o);
            if (lane == 0) {
                float d = (zz + g_c2[cc]) - 2.0f * m;
                unsigned long long p =
                    ((unsigned long long)__float_as_uint(d) << 32) | (unsigned)cc;
                best = (p < best) ? p : best;
            }
        }
    }
    if (lane == 0) g_best[w] = best;
}

// ---------------------------------------------------------------- outputs
__global__ void k_output(const float* __restrict__ z, const float* __restrict__ cb,
                         float* __restrict__ out, int out_size) {
    int w = (blockIdx.x * blockDim.x + threadIdx.x) >> 5, lane = threadIdx.x & 31;
    if (w >= M_ROWS) return;
    int idx = (int)(g_best[w] & 0xFFFFFFFFULL);
    if (lane == 0) {
        int p = OUT_IDX_POS + w;
        if (p < out_size) out[p] = (float)idx;
    }
    const float* zr = z + (size_t)w * K_DIM;
    const float* qr = cb + (size_t)idx * K_DIM;
    float* orow = out + (size_t)w * K_DIM;
    float s = 0.f;
    #pragma unroll 4
    for (int j = lane; j < K_DIM; j += 32) {
        float zv = zr[j], qv = qr[j];
        orow[j] = zv + (qv - zv);
        float dl = zv - qv;
        s = fmaf(dl, dl, s);
    }
    #pragma unroll
    for (int o = 16; o > 0; o >>= 1) s += __shfl_down_sync(0xffffffffu, s, o);
    if (lane == 0) g_rowloss[w] = s;
}
__global__ void k_loss(float* __restrict__ out, int out_size) {
    __shared__ double sd[256];
    int t = threadIdx.x;
    double s = 0.0;
    for (int i = t; i < M_ROWS; i += 256) s += (double)g_rowloss[i];
    sd[t] = s;
    __syncthreads();
    #pragma unroll
    for (int off = 128; off > 0; off >>= 1) {
        if (t < off) sd[t] += sd[t + off];
        __syncthreads();
    }
    if (t == 0 && OUT_LOSS_POS < out_size) {
        double mean = sd[0] / (double)OUT_Q_ELEMS;
        float Mf = (float)mean;
        out[OUT_LOSS_POS] = 0.25f * Mf + Mf;
    }
}

// ---------------------------------------------------------------- launch
extern "C" void kernel_launch(void* const* d_in, const int* in_sizes, int n_in,
                              void* d_out, int out_size) {
    const float* z  = (const float*)d_in[0];
    const float* cb = (const float*)d_in[1];
    float* out = (float*)d_out;
    (void)in_sizes; (void)n_in;

    cudaFuncSetAttribute(k_gemm, cudaFuncAttributeMaxDynamicSharedMemorySize, SMEM_DYN);

    k_prep_z<<<M_ROWS, 256>>>(z);
    k_prep_c<<<(N_CODES * K_DIM / 4) / 256, 256>>>(cb);
    k_rownorm_c_exact<<<(N_CODES * 32 + 255) / 256, 256>>>(cb);

    dim3 grid(N_CODES / TN, M_ROWS / TM);   // (32, 128)
    k_gemm<<<grid, NTHREADS, SMEM_DYN>>>();

    k_scan<<<(M_ROWS * 32) / 256, 256>>>();
    k_recheck<<<(M_ROWS * 32) / 256, 256>>>(z, cb);
    k_output<<<(M_ROWS * 32 + 255) / 256, 256>>>(z, cb, out, out_size);
    k_loss<<<1, 256>>>(out, out_size);
}

// round 7
// speedup vs baseline: 1.0863x; 1.0641x over previous
#include <cuda_runtime.h>
#include <cuda_bf16.h>
#include <cstdint>

// VQ encoder, int8-IMMA, fragment-preload + KC=128 edition.
//  1) fused per-row stats + int8 quant of z; codebook quant + exact c2
//  2) IMMA s8 GEMM (128x256 tiles, 512 thr, KC=128, 2-stage cp.async, ldsm-preload):
//     s = c2 - dq_r*dot -> g_sb (bf16), per-row fp32 min
//  3) scan: candidates with s <= rowmin + TAU
//  4) exact fp32 recheck (R1's verified expression + packed first-index tie-break)
//  5) outputs: quantized_st, loss, indices

#define M_ROWS 16384
#define N_CODES 8192
#define K_DIM   1024
#define OUT_Q_ELEMS 16777216
#define OUT_LOSS_POS 16777216
#define OUT_IDX_POS  16777217

#define CAP 512
#define TAU 1.5e-3f

#define TM 128
#define TN 256
#define KC 128
#define NKC (K_DIM / KC)      // 8
#define BSTRIDE 144           // 128B payload + 16B pad (conflict-free ldmatrix)
#define NSTAGE 2
#define STAGE_BYTES ((TM + TN) * BSTRIDE)       // 55296
#define SMEM_DYN (NSTAGE * STAGE_BYTES)         // 110592
#define NTHREADS 512

// ---------------------------------------------------------------- device scratch
__device__ int8_t g_z8[(size_t)M_ROWS * K_DIM];          // 16 MB
__device__ int8_t g_c8[(size_t)N_CODES * K_DIM];         // 8 MB
__device__ __nv_bfloat16 g_sb[(size_t)M_ROWS * N_CODES]; // 256 MB
__device__ unsigned g_sminu[M_ROWS];
__device__ int g_ccnt[M_ROWS];
__device__ int g_cand[(size_t)M_ROWS * CAP];
__device__ unsigned long long g_best[M_ROWS];
__device__ float g_z2[M_ROWS];
__device__ float g_zdq[M_ROWS];
__device__ float g_c2[N_CODES];
__device__ float g_rowloss[M_ROWS];

// ---------------------------------------------------------------- helpers
__device__ __forceinline__ uint32_t smem_u32(const void* p) {
    uint32_t a;
    asm("{ .reg .u64 t; cvta.to.shared.u64 t, %1; cvt.u32.u64 %0, t; }" : "=r"(a) : "l"(p));
    return a;
}
__device__ __forceinline__ void cp_async16(uint32_t dst, const void* src) {
    asm volatile("cp.async.cg.shared.global [%0], [%1], 16;" :: "r"(dst), "l"(src) : "memory");
}
__device__ __forceinline__ unsigned fmap(float f) {
    unsigned b = __float_as_uint(f);
    return (b & 0x80000000u) ? ~b : (b | 0x80000000u);
}
__device__ __forceinline__ float funmap(unsigned u) {
    return (u & 0x80000000u) ? __uint_as_float(u & 0x7FFFFFFFu) : __uint_as_float(~u);
}
__device__ __forceinline__ void mma_s8(int* c, const uint32_t* a, uint32_t b0, uint32_t b1) {
    asm volatile(
        "mma.sync.aligned.m16n8k32.row.col.s32.s8.s8.s32 "
        "{%0,%1,%2,%3}, {%4,%5,%6,%7}, {%8,%9}, {%0,%1,%2,%3};"
        : "+r"(c[0]), "+r"(c[1]), "+r"(c[2]), "+r"(c[3])
        : "r"(a[0]), "r"(a[1]), "r"(a[2]), "r"(a[3]), "r"(b0), "r"(b1));
}
__device__ __forceinline__ void ldsm4(uint32_t* r, uint32_t addr) {
    asm volatile("ldmatrix.sync.aligned.m8n8.x4.shared.b16 {%0,%1,%2,%3}, [%4];"
        : "=r"(r[0]), "=r"(r[1]), "=r"(r[2]), "=r"(r[3]) : "r"(addr));
}

// ---------------------------------------------------------------- fused prep
__global__ void __launch_bounds__(256) k_prep_z(const float* __restrict__ z) {
    __shared__ float ssum[8], smax[8];
    int row = blockIdx.x, t = threadIdx.x, lane = t & 31, wid = t >> 5;
    float4 v = ((const float4*)(z + (size_t)row * K_DIM))[t];
    float s = v.x*v.x + v.y*v.y + v.z*v.z + v.w*v.w;
    float mx = fmaxf(fmaxf(fabsf(v.x), fabsf(v.y)), fmaxf(fabsf(v.z), fabsf(v.w)));
    #pragma unroll
    for (int o = 16; o > 0; o >>= 1) {
        s  += __shfl_down_sync(0xffffffffu, s, o);
        mx = fmaxf(mx, __shfl_down_sync(0xffffffffu, mx, o));
    }
    if (lane == 0) { ssum[wid] = s; smax[wid] = mx; }
    __syncthreads();
    if (t == 0) {
        float ts = 0.f, tm = 0.f;
        #pragma unroll
        for (int i = 0; i < 8; i++) { ts += ssum[i]; tm = fmaxf(tm, smax[i]); }
        tm = fmaxf(tm, 1e-20f);
        g_z2[row] = ts;
        g_zdq[row] = 2.f * tm / (127.f * 127.f * 8192.f);
        ssum[0] = 127.f / tm;
        g_sminu[row] = 0xFFFFFFFFu;
        g_ccnt[row] = 0;
    }
    __syncthreads();
    float sc = ssum[0];
    char4 o;
    o.x = (char)__float2int_rn(v.x * sc);
    o.y = (char)__float2int_rn(v.y * sc);
    o.z = (char)__float2int_rn(v.z * sc);
    o.w = (char)__float2int_rn(v.w * sc);
    ((char4*)(g_z8 + (size_t)row * K_DIM))[t] = o;
}

__global__ void __launch_bounds__(256) k_prep_c(const float* __restrict__ cb) {
    int i = blockIdx.x * blockDim.x + threadIdx.x;
    const float sc = 127.f * 8192.f;
    float4 v = ((const float4*)cb)[i];
    char4 o;
    o.x = (char)__float2int_rn(v.x * sc);
    o.y = (char)__float2int_rn(v.y * sc);
    o.z = (char)__float2int_rn(v.z * sc);
    o.w = (char)__float2int_rn(v.w * sc);
    ((char4*)g_c8)[i] = o;
}

// exact c2 in R1's verified accumulation order (feeds exact recheck)
__global__ void k_rownorm_c_exact(const float* __restrict__ cb) {
    int w = (blockIdx.x * blockDim.x + threadIdx.x) >> 5, lane = threadIdx.x & 31;
    if (w >= N_CODES) return;
    const float* r = cb + (size_t)w * K_DIM;
    float s = 0.f;
    #pragma unroll 4
    for (int j = lane; j < K_DIM; j += 32) { float v = r[j]; s = fmaf(v, v, s); }
    #pragma unroll
    for (int o = 16; o > 0; o >>= 1) s += __shfl_down_sync(0xffffffffu, s, o);
    if (lane == 0) g_c2[w] = s;
}

// ---------------------------------------------------------------- IMMA GEMM
// 128x256 tile, 512 threads (16 warps, 4x4 -> warp tile 32x64), KC=128, 2-stage.
__global__ void __launch_bounds__(NTHREADS, 1) k_gemm() {
    extern __shared__ uint8_t dynsm[];
    __shared__ float sC2[TN];

    const int t = threadIdx.x;
    const int wid = t >> 5, lane = t & 31;
    const int warpm = (wid & 3) * 32;        // 4 warps over M
    const int warpn = (wid >> 2) * 64;       // 4 warps over N
    const int colBase = blockIdx.x * TN;
    const int rowBase = blockIdx.y * TM;

    if (t < TN) sC2[t] = g_c2[colBase + t];

    int acc[2][8][4];
    #pragma unroll
    for (int mf = 0; mf < 2; mf++)
        #pragma unroll
        for (int nf = 0; nf < 8; nf++)
            #pragma unroll
            for (int q = 0; q < 4; q++) acc[mf][nf][q] = 0;

    auto sA = [&](int s) -> uint8_t* { return dynsm + s * STAGE_BYTES; };
    auto sB = [&](int s) -> uint8_t* { return dynsm + s * STAGE_BYTES + TM * BSTRIDE; };

    // loader: 512 threads, 16B each: A 128x128B = 2 passes of 64 rows? No:
    // 512 thr * 16B = 8KB/pass. A stage = 16KB -> 2 passes; B stage = 32KB -> 4 passes.
    const int lrow = t >> 3, lq = t & 7;     // 64 rows per pass, 8x16B chunks per row
    auto load_stage = [&](int s, int c) {
        int kc = c * KC;
        #pragma unroll
        for (int u = 0; u < 2; u++) {
            int row = lrow + u * 64;
            cp_async16(smem_u32(sA(s) + row * BSTRIDE + lq * 16),
                       &g_z8[(size_t)(rowBase + row) * K_DIM + kc + lq * 16]);
        }
        #pragma unroll
        for (int u = 0; u < 4; u++) {
            int row = lrow + u * 64;
            cp_async16(smem_u32(sB(s) + row * BSTRIDE + lq * 16),
                       &g_c8[(size_t)(colBase + row) * K_DIM + kc + lq * 16]);
        }
        asm volatile("cp.async.commit_group;" ::: "memory");
    };

    load_stage(0, 0);
    for (int c = 0; c < NKC; c++) {
        if (c + 1 < NKC) {
            load_stage((c + 1) & 1, c + 1);
            asm volatile("cp.async.wait_group 1;" ::: "memory");
        } else {
            asm volatile("cp.async.wait_group 0;" ::: "memory");
        }
        __syncthreads();
        int s = c & 1;
        #pragma unroll
        for (int ks = 0; ks < 4; ks++) {
            int kk = ks * 32;
            // ---- preload ALL fragments for this k32 step, then mma ----
            uint32_t afr[2][4], bfr[4][4];
            #pragma unroll
            for (int mf = 0; mf < 2; mf++) {
                int row = warpm + mf * 16 + (lane & 15);
                int col = kk + ((lane >> 4) << 4);
                ldsm4(afr[mf], smem_u32(sA(s) + row * BSTRIDE + col));
            }
            int grp = lane >> 3, lr = lane & 7;
            #pragma unroll
            for (int np = 0; np < 4; np++) {
                int nrow = warpn + np * 16 + ((grp >> 1) << 3) + lr;
                int kcol = kk + ((grp & 1) << 4);
                ldsm4(bfr[np], smem_u32(sB(s) + nrow * BSTRIDE + kcol));
            }
            #pragma unroll
            for (int np = 0; np < 4; np++)
                #pragma unroll
                for (int mf = 0; mf < 2; mf++) {
                    mma_s8(acc[mf][np * 2 + 0], afr[mf], bfr[np][0], bfr[np][1]);
                    mma_s8(acc[mf][np * 2 + 1], afr[mf], bfr[np][2], bfr[np][3]);
                }
        }
        __syncthreads();
    }

    // epilogue: s = c2 - dq_row * dot ; store bf16 ; per-row fp32 min
    #pragma unroll
    for (int mf = 0; mf < 2; mf++) {
        int row0 = rowBase + warpm + mf * 16 + (lane >> 2);
        float dq0 = g_zdq[row0], dq1 = g_zdq[row0 + 8];
        float v0 = 3.4e38f, v1 = 3.4e38f;
        #pragma unroll
        for (int nf = 0; nf < 8; nf++) {
            int lc = warpn + nf * 8 + (lane & 3) * 2;
            float c2a = sC2[lc], c2b = sC2[lc + 1];
            float s0 = c2a - dq0 * (float)acc[mf][nf][0];
            float s1 = c2b - dq0 * (float)acc[mf][nf][1];
            float s2 = c2a - dq1 * (float)acc[mf][nf][2];
            float s3 = c2b - dq1 * (float)acc[mf][nf][3];
            *(__nv_bfloat162*)&g_sb[(size_t)row0 * N_CODES + colBase + lc] =
                __nv_bfloat162(__float2bfloat16(s0), __float2bfloat16(s1));
            *(__nv_bfloat162*)&g_sb[(size_t)(row0 + 8) * N_CODES + colBase + lc] =
                __nv_bfloat162(__float2bfloat16(s2), __float2bfloat16(s3));
            v0 = fminf(v0, fminf(s0, s1));
            v1 = fminf(v1, fminf(s2, s3));
        }
        v0 = fminf(v0, __shfl_xor_sync(0xffffffffu, v0, 1));
        v0 = fminf(v0, __shfl_xor_sync(0xffffffffu, v0, 2));
        v1 = fminf(v1, __shfl_xor_sync(0xffffffffu, v1, 1));
        v1 = fminf(v1, __shfl_xor_sync(0xffffffffu, v1, 2));
        if ((lane & 3) == 0) {
            atomicMin(&g_sminu[row0], fmap(v0));
            atomicMin(&g_sminu[row0 + 8], fmap(v1));
        }
    }
}

// ---------------------------------------------------------------- candidate scan
__global__ void k_scan() {
    int w = (blockIdx.x * blockDim.x + threadIdx.x) >> 5, lane = threadIdx.x & 31;
    if (w >= M_ROWS) return;
    float thr = funmap(g_sminu[w]) + TAU;
    const uint4* srow = (const uint4*)(g_sb + (size_t)w * N_CODES);
    for (int cidx = lane; cidx < N_CODES / 8; cidx += 32) {
        uint4 u = srow[cidx];
        uint32_t words[4] = {u.x, u.y, u.z, u.w};
        #pragma unroll
        for (int q = 0; q < 4; q++) {
            __nv_bfloat162 p = *(__nv_bfloat162*)&words[q];
            float a = __bfloat162float(p.x), b = __bfloat162float(p.y);
            if (a <= thr) {
                int slot = atomicAdd(&g_ccnt[w], 1);
                if (slot < CAP) g_cand[(size_t)w * CAP + slot] = cidx * 8 + q * 2;
            }
            if (b <= thr) {
                int slot = atomicAdd(&g_ccnt[w], 1);
                if (slot < CAP) g_cand[(size_t)w * CAP + slot] = cidx * 8 + q * 2 + 1;
            }
        }
    }
}

// ---------------------------------------------------------------- exact recheck
__global__ void k_recheck(const float* __restrict__ z, const float* __restrict__ cb) {
    int w = (blockIdx.x * blockDim.x + threadIdx.x) >> 5, lane = threadIdx.x & 31;
    if (w >= M_ROWS) return;
    const float* zr = z + (size_t)w * K_DIM;
    float zz = g_z2[w];
    int n = g_ccnt[w];
    unsigned long long best = ~0ULL;
    if (n <= CAP) {
        for (int i = 0; i < n; i++) {
            int cc = g_cand[(size_t)w * CAP + i];
            const float* cr = cb + (size_t)cc * K_DIM;
            float m = 0.f;
            #pragma unroll 4
            for (int j = lane; j < K_DIM; j += 32) m = fmaf(zr[j], cr[j], m);
            #pragma unroll
            for (int o = 16; o > 0; o >>= 1) m += __shfl_down_sync(0xffffffffu, m, o);
            if (lane == 0) {
                float d = (zz + g_c2[cc]) - 2.0f * m;
                unsigned long long p =
                    ((unsigned long long)__float_as_uint(d) << 32) | (unsigned)cc;
                best = (p < best) ? p : best;
            }
        }
    } else {
        for (int cc = 0; cc < N_CODES; cc++) {
            const float* cr = cb + (size_t)cc * K_DIM;
            float m = 0.f;
            for (int j = lane; j < K_DIM; j += 32) m = fmaf(zr[j], cr[j], m);
            #pragma unroll
            for (int o = 16; o > 0; o >>= 1) m += __shfl_down_sync(0xffffffffu, m, o);
            if (lane == 0) {
                float d = (zz + g_c2[cc]) - 2.0f * m;
                unsigned long long p =
                    ((unsigned long long)__float_as_uint(d) << 32) | (unsigned)cc;
                best = (p < best) ? p : best;
            }
        }
    }
    if (lane == 0) g_best[w] = best;
}

// ---------------------------------------------------------------- outputs
__global__ void k_output(const float* __restrict__ z, const float* __restrict__ cb,
                         float* __restrict__ out, int out_size) {
    int w = (blockIdx.x * blockDim.x + threadIdx.x) >> 5, lane = threadIdx.x & 31;
    if (w >= M_ROWS) return;
    int idx = (int)(g_best[w] & 0xFFFFFFFFULL);
    if (lane == 0) {
        int p = OUT_IDX_POS + w;
        if (p < out_size) out[p] = (float)idx;
    }
    const float* zr = z + (size_t)w * K_DIM;
    const float* qr = cb + (size_t)idx * K_DIM;
    float* orow = out + (size_t)w * K_DIM;
    float s = 0.f;
    #pragma unroll 4
    for (int j = lane; j < K_DIM; j += 32) {
        float zv = zr[j], qv = qr[j];
        orow[j] = zv + (qv - zv);
        float dl = zv - qv;
        s = fmaf(dl, dl, s);
    }
    #pragma unroll
    for (int o = 16; o > 0; o >>= 1) s += __shfl_down_sync(0xffffffffu, s, o);
    if (lane == 0) g_rowloss[w] = s;
}
__global__ void k_loss(float* __restrict__ out, int out_size) {
    __shared__ double sd[256];
    int t = threadIdx.x;
    double s = 0.0;
    for (int i = t; i < M_ROWS; i += 256) s += (double)g_rowloss[i];
    sd[t] = s;
    __syncthreads();
    #pragma unroll
    for (int off = 128; off > 0; off >>= 1) {
        if (t < off) sd[t] += sd[t + off];
        __syncthreads();
    }
    if (t == 0 && OUT_LOSS_POS < out_size) {
        double mean = sd[0] / (double)OUT_Q_ELEMS;
        float Mf = (float)mean;
        out[OUT_LOSS_POS] = 0.25f * Mf + Mf;
    }
}

// ---------------------------------------------------------------- launch
extern "C" void kernel_launch(void* const* d_in, const int* in_sizes, int n_in,
                              void* d_out, int out_size) {
    const float* z  = (const float*)d_in[0];
    const float* cb = (const float*)d_in[1];
    float* out = (float*)d_out;
    (void)in_sizes; (void)n_in;

    cudaFuncSetAttribute(k_gemm, cudaFuncAttributeMaxDynamicSharedMemorySize, SMEM_DYN);

    k_prep_z<<<M_ROWS, 256>>>(z);
    k_prep_c<<<(N_CODES * K_DIM / 4) / 256, 256>>>(cb);
    k_rownorm_c_exact<<<(N_CODES * 32 + 255) / 256, 256>>>(cb);

    dim3 grid(N_CODES / TN, M_ROWS / TM);   // (32, 128)
    k_gemm<<<grid, NTHREADS, SMEM_DYN>>>();

    k_scan<<<(M_ROWS * 32) / 256, 256>>>();
    k_recheck<<<(M_ROWS * 32) / 256, 256>>>(z, cb);
    k_output<<<(M_ROWS * 32 + 255) / 256, 256>>>(z, cb, out, out_size);
    k_loss<<<1, 256>>>(out, out_size);
}